// round 10
// baseline (speedup 1.0000x reference)
#include <cuda_runtime.h>
#include <cstdint>

#define NMAX 50048
#define EMAX 800000
#define DD   128
#define AS_LD 132   // padded A-tile row (floats): 132*4 % 16 == 0, bank-safe

// ---------------- static device scratch ----------------
__device__ int   g_mode;
__device__ int   g_deg[NMAX + 1];
__device__ int   g_rowstart[NMAX + 1];
__device__ int   g_cursor[NMAX + 1];
__device__ int   g_csr[EMAX];
__device__ float g_t1[(size_t)NMAX * DD];   // relu(z@W1+b1)
__device__ float g_t2[(size_t)NMAX * DD];   // t1@W2+b2 (pre-BN)
__device__ float g_sum[DD], g_sq[DD];

// ---------------- packed f32x2 helpers ----------------
__device__ __forceinline__ unsigned long long pack2(float lo, float hi) {
    unsigned long long r;
    asm("mov.b64 %0, {%1, %2};" : "=l"(r) : "f"(lo), "f"(hi));
    return r;
}
__device__ __forceinline__ unsigned long long splat2(float a) {
    unsigned long long r;
    asm("mov.b64 %0, {%1, %1};" : "=l"(r) : "f"(a));
    return r;
}
__device__ __forceinline__ void fma2(unsigned long long& acc,
                                     unsigned long long a, unsigned long long b) {
    asm("fma.rn.f32x2 %0, %1, %2, %0;" : "+l"(acc) : "l"(a), "l"(b));
}
__device__ __forceinline__ float2 unpack2(unsigned long long v) {
    float2 r;
    asm("mov.b64 {%0, %1}, %2;" : "=f"(r.x), "=f"(r.y) : "l"(v));
    return r;
}

// ---------------- CSR build ----------------
__global__ void init_kernel(const void* ei, int n) {
    int i = blockIdx.x * blockDim.x + threadIdx.x;
    if (i <= n) g_deg[i] = 0;
    if (blockIdx.x == 0 && threadIdx.x < 32) {
        const int* p = (const int*)ei;
        int v = p[2 * threadIdx.x + 1];
        unsigned b = __ballot_sync(0xffffffffu, v == 0);
        if (threadIdx.x == 0) g_mode = (b == 0xffffffffu) ? 1 : 0;
    }
}

// 2 edges per thread, vectorized loads (ATOMG is 318-cyc latency-bound:
// double the per-thread MLP).
__global__ void hist_kernel(const void* ei, int E) {
    int base = (blockIdx.x * blockDim.x + threadIdx.x) * 2;
    if (base >= E) return;
    int d0, d1;
    bool two = (base + 1 < E);
    if (g_mode) {
        const longlong2* p = (const longlong2*)((const long long*)ei + E + base);
        longlong2 v = *p;
        d0 = (int)v.x; d1 = (int)v.y;
    } else {
        const int2* p = (const int2*)((const int*)ei + E + base);
        int2 v = *p;
        d0 = v.x; d1 = v.y;
    }
    atomicAdd(&g_deg[d0], 1);
    if (two) atomicAdd(&g_deg[d1], 1);
}

__global__ void scan_kernel(int n) {
    __shared__ int sh[1024];
    int tid = threadIdx.x;
    int chunk = (n + 1023) >> 10;
    int a = tid * chunk; if (a > n) a = n;
    int b = a + chunk;   if (b > n) b = n;
    int s = 0;
    for (int i = a; i < b; i++) s += g_deg[i];
    sh[tid] = s;
    __syncthreads();
    for (int off = 1; off < 1024; off <<= 1) {
        int v = (tid >= off) ? sh[tid - off] : 0;
        __syncthreads();
        sh[tid] += v;
        __syncthreads();
    }
    int run = sh[tid] - s;
    for (int i = a; i < b; i++) {
        g_rowstart[i] = run;
        g_cursor[i]   = run;
        run += g_deg[i];
    }
    if (tid == 1023) g_rowstart[n] = sh[1023];
}

__global__ void scatter_kernel(const void* ei, int E) {
    int base = (blockIdx.x * blockDim.x + threadIdx.x) * 2;
    if (base >= E) return;
    int s0, s1, d0, d1;
    bool two = (base + 1 < E);
    if (g_mode) {
        const long long* p = (const long long*)ei;
        longlong2 sv = *(const longlong2*)(p + base);
        longlong2 dv = *(const longlong2*)(p + E + base);
        s0 = (int)sv.x; s1 = (int)sv.y; d0 = (int)dv.x; d1 = (int)dv.y;
    } else {
        const int* p = (const int*)ei;
        int2 sv = *(const int2*)(p + base);
        int2 dv = *(const int2*)(p + E + base);
        s0 = sv.x; s1 = sv.y; d0 = dv.x; d1 = dv.y;
    }
    int p0 = atomicAdd(&g_cursor[d0], 1);
    int p1 = two ? atomicAdd(&g_cursor[d1], 1) : 0;
    g_csr[p0] = s0;
    if (two) g_csr[p1] = s1;
}

// ---------------- fused aggregation + GEMM1 ----------------
// Per CTA: gather z = x + sum_nbr(x) for 128 rows straight into smem A tile
// (row-major, padded to AS_LD), then C = relu(z @ W1 + b1) -> g_t1.
// Eliminates the g_z gmem round-trip; gather of one resident CTA overlaps
// FFMA2 compute of the other.
__global__ void __launch_bounds__(256, 2) fused_agg_gemm1(
    const float* __restrict__ x, const float* __restrict__ W,
    const float* __restrict__ bias, int n)
{
    extern __shared__ float sm[];
    float* As = sm;                       // [128][AS_LD]
    float* Bs = sm + 128 * AS_LD;         // [2][16][128]

    int t    = threadIdx.x;
    int wid  = t >> 5, lane = t & 31;
    int m0   = blockIdx.x * 128;

    if (blockIdx.x == 0 && t < DD) { g_sum[t] = 0.f; g_sq[t] = 0.f; }

    // prefetch B k-tile 0 into regs
    float4 pb[2];
    {
#pragma unroll
        for (int i = 0; i < 2; i++) {
            int f = i * 256 + t;
            pb[i] = *(const float4*)&W[(size_t)(f >> 5) * 128 + (f & 31) * 4];
        }
    }

    // gather: warp wid handles rows wid*16 .. wid*16+15
    const float4* __restrict__ X = (const float4*)x;
    for (int r = 0; r < 16; r++) {
        int row  = wid * 16 + r;
        int node = m0 + row;
        float4 a = make_float4(0.f, 0.f, 0.f, 0.f);
        if (node < n) {
            a = X[(size_t)node * 32 + lane];
            int e  = g_rowstart[node];
            int e1 = g_rowstart[node + 1];
            for (; e + 3 < e1; e += 4) {
                int s0 = g_csr[e], s1 = g_csr[e + 1], s2 = g_csr[e + 2], s3 = g_csr[e + 3];
                float4 v0 = X[(size_t)s0 * 32 + lane];
                float4 v1 = X[(size_t)s1 * 32 + lane];
                float4 v2 = X[(size_t)s2 * 32 + lane];
                float4 v3 = X[(size_t)s3 * 32 + lane];
                a.x += v0.x; a.y += v0.y; a.z += v0.z; a.w += v0.w;
                a.x += v1.x; a.y += v1.y; a.z += v1.z; a.w += v1.w;
                a.x += v2.x; a.y += v2.y; a.z += v2.z; a.w += v2.w;
                a.x += v3.x; a.y += v3.y; a.z += v3.z; a.w += v3.w;
            }
            for (; e < e1; e++) {
                int s0 = g_csr[e];
                float4 v0 = X[(size_t)s0 * 32 + lane];
                a.x += v0.x; a.y += v0.y; a.z += v0.z; a.w += v0.w;
            }
        }
        *(float4*)&As[row * AS_LD + lane * 4] = a;
    }
    __syncthreads();
    // commit B tile 0
#pragma unroll
    for (int i = 0; i < 2; i++) {
        int f = i * 256 + t;
        *(float4*)&Bs[(f >> 5) * 128 + (f & 31) * 4] = pb[i];
    }
    __syncthreads();

    int tx = t & 15;   // N: cols tx*8 .. +7
    int ty = t >> 4;   // M: rows ty*8 .. +7

    unsigned long long acc[8][4];
    {
        float bv[8];
#pragma unroll
        for (int j = 0; j < 8; j++) bv[j] = bias[tx * 8 + j];
#pragma unroll
        for (int i = 0; i < 8; i++)
#pragma unroll
            for (int j = 0; j < 4; j++)
                acc[i][j] = pack2(bv[2 * j], bv[2 * j + 1]);
    }

    const float* aRow = As + (size_t)ty * 8 * AS_LD;

#pragma unroll
    for (int it = 0; it < 8; it++) {
        int cur = it & 1;
        if (it < 7) {
            int k0 = (it + 1) * 16;
#pragma unroll
            for (int i = 0; i < 2; i++) {
                int f = i * 256 + t;
                pb[i] = *(const float4*)&W[(size_t)(k0 + (f >> 5)) * 128 + (f & 31) * 4];
            }
        }
        const float* bBase = Bs + cur * 2048;
#pragma unroll
        for (int kk = 0; kk < 16; kk++) {
            int kg = it * 16 + kk;
            unsigned long long b2[4];
            const unsigned long long* br =
                (const unsigned long long*)(bBase + kk * 128 + tx * 8);
#pragma unroll
            for (int j = 0; j < 4; j++) b2[j] = br[j];
#pragma unroll
            for (int h = 0; h < 2; h++) {
                unsigned long long a2[4];
#pragma unroll
                for (int i = 0; i < 4; i++)
                    a2[i] = splat2(aRow[(h * 4 + i) * AS_LD + kg]);
#pragma unroll
                for (int i = 0; i < 4; i++)
#pragma unroll
                    for (int j = 0; j < 4; j++)
                        fma2(acc[h * 4 + i][j], a2[i], b2[j]);
            }
        }
        if (it < 7) {
            int nxt = cur ^ 1;
#pragma unroll
            for (int i = 0; i < 2; i++) {
                int f = i * 256 + t;
                *(float4*)&Bs[nxt * 2048 + (f >> 5) * 128 + (f & 31) * 4] = pb[i];
            }
            __syncthreads();
        }
    }

    // epilogue: relu -> g_t1
#pragma unroll
    for (int i = 0; i < 8; i++) {
        int row = m0 + ty * 8 + i;
        if (row < n) {
            float v[8];
#pragma unroll
            for (int j = 0; j < 4; j++) {
                float2 c = unpack2(acc[i][j]);
                v[2 * j] = fmaxf(c.x, 0.f); v[2 * j + 1] = fmaxf(c.y, 0.f);
            }
            *(float4*)&g_t1[(size_t)row * 128 + tx * 8]     = make_float4(v[0], v[1], v[2], v[3]);
            *(float4*)&g_t1[(size_t)row * 128 + tx * 8 + 4] = make_float4(v[4], v[5], v[6], v[7]);
        }
    }
}

// ---------------- GEMM2: t2 = t1 @ W2 + b2, with BN column stats ----------------
__global__ void __launch_bounds__(256, 2) gemm2_kernel(
    const float* __restrict__ W, const float* __restrict__ bias, int M)
{
    const float* __restrict__ A = g_t1;
    float* __restrict__ C       = g_t2;

    __shared__ float As[2][16][128];
    __shared__ float Bs[2][16][128];
    __shared__ float ssum[128], ssq[128];

    int t  = threadIdx.x;
    int tx = t & 15;
    int ty = t >> 4;
    int m0 = blockIdx.x * 128;

    unsigned long long acc[8][4];
    {
        float bv[8];
#pragma unroll
        for (int j = 0; j < 8; j++) bv[j] = bias[tx * 8 + j];
#pragma unroll
        for (int i = 0; i < 8; i++)
#pragma unroll
            for (int j = 0; j < 4; j++)
                acc[i][j] = pack2(bv[2 * j], bv[2 * j + 1]);
    }

    float4 pa[2], pb[2];
    auto loadA = [&](int k0) {
#pragma unroll
        for (int i = 0; i < 2; i++) {
            int f = i * 256 + t;
            int m = f >> 2, q = (f & 3) * 4;
            int row = m0 + m;
            if (row < M) pa[i] = *(const float4*)&A[(size_t)row * 128 + k0 + q];
            else         pa[i] = make_float4(0.f, 0.f, 0.f, 0.f);
        }
    };
    auto loadB = [&](int k0) {
#pragma unroll
        for (int i = 0; i < 2; i++) {
            int f = i * 256 + t;
            int k = f >> 5, n4 = (f & 31) * 4;
            pb[i] = *(const float4*)&W[(size_t)(k0 + k) * 128 + n4];
        }
    };
    auto storeTile = [&](int buf) {
#pragma unroll
        for (int i = 0; i < 2; i++) {
            int f = i * 256 + t;
            int m = f >> 2, q = (f & 3) * 4;
            As[buf][q + 0][m] = pa[i].x;
            As[buf][q + 1][m] = pa[i].y;
            As[buf][q + 2][m] = pa[i].z;
            As[buf][q + 3][m] = pa[i].w;
            int k = f >> 5, n4 = (f & 31) * 4;
            *(float4*)&Bs[buf][k][n4] = pb[i];
        }
    };

    loadA(0); loadB(0);
    storeTile(0);
    __syncthreads();

#pragma unroll
    for (int it = 0; it < 8; it++) {
        int cur = it & 1;
        if (it < 7) { loadA((it + 1) * 16); loadB((it + 1) * 16); }

#pragma unroll
        for (int kk = 0; kk < 16; kk++) {
            unsigned long long b2[4];
            const unsigned long long* br =
                (const unsigned long long*)&Bs[cur][kk][tx * 8];
#pragma unroll
            for (int j = 0; j < 4; j++) b2[j] = br[j];
#pragma unroll
            for (int h = 0; h < 2; h++) {
                float4 av = *(const float4*)&As[cur][kk][ty * 8 + h * 4];
                unsigned long long a2[4];
                a2[0] = splat2(av.x); a2[1] = splat2(av.y);
                a2[2] = splat2(av.z); a2[3] = splat2(av.w);
#pragma unroll
                for (int i = 0; i < 4; i++)
#pragma unroll
                    for (int j = 0; j < 4; j++)
                        fma2(acc[h * 4 + i][j], a2[i], b2[j]);
            }
        }

        if (it < 7) {
            storeTile(cur ^ 1);
            __syncthreads();
        }
    }

    __syncthreads();
    if (t < 128) { ssum[t] = 0.f; ssq[t] = 0.f; }
    __syncthreads();

    float ts[8], tq[8];
#pragma unroll
    for (int j = 0; j < 8; j++) { ts[j] = 0.f; tq[j] = 0.f; }

#pragma unroll
    for (int i = 0; i < 8; i++) {
        int row = m0 + ty * 8 + i;
        if (row < M) {
            float v[8];
#pragma unroll
            for (int j = 0; j < 4; j++) {
                float2 c = unpack2(acc[i][j]);
                v[2 * j] = c.x; v[2 * j + 1] = c.y;
            }
#pragma unroll
            for (int j = 0; j < 8; j++) { ts[j] += v[j]; tq[j] += v[j] * v[j]; }
            *(float4*)&C[(size_t)row * 128 + tx * 8]     = make_float4(v[0], v[1], v[2], v[3]);
            *(float4*)&C[(size_t)row * 128 + tx * 8 + 4] = make_float4(v[4], v[5], v[6], v[7]);
        }
    }

#pragma unroll
    for (int j = 0; j < 8; j++) {
        atomicAdd(&ssum[tx * 8 + j], ts[j]);
        atomicAdd(&ssq [tx * 8 + j], tq[j]);
    }
    __syncthreads();
    if (t < 128) {
        atomicAdd(&g_sum[t], ssum[t]);
        atomicAdd(&g_sq [t], ssq [t]);
    }
}

// ---------------- norm: BN finalize folded in + relu -> out ----------------
__global__ void norm_kernel(float* __restrict__ outp,
                            const float* __restrict__ gamma,
                            const float* __restrict__ beta,
                            float invN, int n4) {
    __shared__ float sc[DD], shf[DD];
    int t = threadIdx.x;
    if (t < DD) {
        float mean = g_sum[t] * invN;
        float var  = fmaxf(g_sq[t] * invN - mean * mean, 0.f);
        float s    = gamma[t] * rsqrtf(var + 1e-5f);
        sc[t]  = s;
        shf[t] = beta[t] - mean * s;
    }
    __syncthreads();
    int i = blockIdx.x * blockDim.x + t;
    if (i >= n4) return;
    int c4 = (i & 31) * 4;
    float4 v = ((const float4*)g_t2)[i];
    float4 s = *(float4*)&sc[c4];
    float4 h = *(float4*)&shf[c4];
    v.x = fmaxf(fmaf(v.x, s.x, h.x), 0.f);
    v.y = fmaxf(fmaf(v.y, s.y, h.y), 0.f);
    v.z = fmaxf(fmaf(v.z, s.z, h.z), 0.f);
    v.w = fmaxf(fmaf(v.w, s.w, h.w), 0.f);
    ((float4*)outp)[i] = v;
}

// ------------------------------------------------------------------
extern "C" void kernel_launch(void* const* d_in, const int* in_sizes, int n_in,
                              void* d_out, int out_size) {
    (void)n_in; (void)out_size;
    const float* h     = (const float*)d_in[0];
    const void*  ei    = d_in[1];
    const float* W1    = (const float*)d_in[2];
    const float* b1    = (const float*)d_in[3];
    const float* W2    = (const float*)d_in[4];
    const float* b2    = (const float*)d_in[5];
    const float* gamma = (const float*)d_in[6];
    const float* beta  = (const float*)d_in[7];
    float* out = (float*)d_out;

    int N = in_sizes[0] / DD;          // 50000
    int E = in_sizes[1] / 2;           // 800000
    int L = in_sizes[2] / (DD * DD);   // 2

    const int FUSED_SMEM = (128 * AS_LD + 2 * 16 * 128) * (int)sizeof(float);
    cudaFuncSetAttribute(fused_agg_gemm1,
                         cudaFuncAttributeMaxDynamicSharedMemorySize, FUSED_SMEM);

    // ---- CSR build (shared across layers) ----
    init_kernel<<<(N + 256) / 256, 256>>>(ei, N);
    int ehalf = (E + 1) / 2;
    hist_kernel<<<(ehalf + 255) / 256, 256>>>(ei, E);
    scan_kernel<<<1, 1024>>>(N);
    scatter_kernel<<<(ehalf + 255) / 256, 256>>>(ei, E);

    int gemm_blocks = (N + 127) / 128;
    int n4          = N * 32;
    int norm_blocks = (n4 + 255) / 256;

    for (int l = 0; l < L; l++) {
        const float* x = (l == 0) ? h : (out + (size_t)(l - 1) * N * DD);
        fused_agg_gemm1<<<gemm_blocks, 256, FUSED_SMEM>>>(
            x, W1 + (size_t)l * DD * DD, b1 + (size_t)l * DD, N);
        gemm2_kernel<<<gemm_blocks, 256>>>(W2 + (size_t)l * DD * DD,
                                           b2 + (size_t)l * DD, N);
        norm_kernel<<<norm_blocks, 256>>>(out + (size_t)l * N * DD,
                                          gamma + (size_t)l * DD,
                                          beta + (size_t)l * DD,
                                          1.0f / (float)N, n4);
    }
}